// round 10
// baseline (speedup 1.0000x reference)
#include <cuda_runtime.h>
#include <math.h>

#define NMAX 100000
#define D    512
#define D4   128          // D / 4 (float4 columns)
#define C    100
#define B    512          // sort blocks
#define S1   23           // segments per class, pass 1 (C*S1=2300 < 148*16 — one wave)
#define S2   11           // segments per class, pass 2 (C*S2=1100 < 148*8  — one wave)
#define EPSF 1e-8f

// ---------------- device scratch (static; no allocations allowed) ----------
__device__ int   g_bhist[C * B];   // per-(class, sortblock) counts
__device__ int   g_blocal[C * B];  // exclusive scan of g_bhist within each class
__device__ int   g_ctotal[C];      // per-class totals
__device__ int   g_offset[C];      // class base offsets
__device__ int   g_count[C];
__device__ int   g_done[C];        // classsum segment completion counters
__device__ int   g_sorted[NMAX];
__device__ float g_sum[C * D];
__device__ float g_mean[C * D];
__device__ float g_invn[C];        // 1 / max(||mean_c||, eps)

// Label-dtype probe over the FIXED window [0, min(64,n)) — in-bounds and
// identical in every block. int64 labels in [0,100): odd int32 words all 0.
// Returns element stride in int32 units: 1 for int32, 2 for int64.
__device__ __forceinline__ int probe_stride(const int* __restrict__ l32,
                                            int n, int tid) {
    __shared__ int s_st;
    if (tid < 32) {
        int lim = (n < 64) ? n : 64;
        int any = 0;
        for (int i = tid; i < lim; i += 32)
            any |= l32[2 * (size_t)i + 1];
        any = __any_sync(0xffffffffu, any != 0);
        if (tid == 0) s_st = any ? 1 : 2;
    }
    __syncthreads();
    return s_st;
}

// ---------------- kernel 1: zero sums + per-block class histogram ---------
__global__ void __launch_bounds__(256) k_hist(const int* __restrict__ l32, int n) {
    __shared__ int sh[C];
    int b = blockIdx.x;
    {
        float4* z4 = (float4*)&g_sum[b * 100];   // C*D = B * 100 floats
        for (int i = threadIdx.x; i < 25; i += blockDim.x)
            z4[i] = make_float4(0.f, 0.f, 0.f, 0.f);
    }
    for (int i = threadIdx.x; i < C; i += blockDim.x) sh[i] = 0;
    __syncthreads();

    int st = probe_stride(l32, n, threadIdx.x);
    int chunk = (n + B - 1) / B;
    int lo = b * chunk, hi = min(n, lo + chunk);

    for (int i = lo + threadIdx.x; i < hi; i += blockDim.x)
        atomicAdd(&sh[l32[(size_t)i * st]], 1);
    __syncthreads();
    for (int c = threadIdx.x; c < C; c += blockDim.x)
        g_bhist[c * B + b] = sh[c];
}

// ---------------- kernel 2: per-class exclusive scan over the B blocks ----
__global__ void __launch_bounds__(B) k_scanb() {
    int c = blockIdx.x;
    int t = threadIdx.x;                  // 0..511, 16 warps
    if (t == 0) g_done[c] = 0;
    int v = g_bhist[c * B + t];

    int x = v;
    #pragma unroll
    for (int o = 1; o < 32; o <<= 1) {
        int y = __shfl_up_sync(0xffffffffu, x, o);
        if ((t & 31) >= o) x += y;
    }
    __shared__ int wtot[16];
    int wid = t >> 5, lane = t & 31;
    if (lane == 31) wtot[wid] = x;
    __syncthreads();
    if (t < 16) {
        int w = wtot[t];
        int y = w;
        #pragma unroll
        for (int o = 1; o < 16; o <<= 1) {
            int z = __shfl_up_sync(0x0000ffffu, y, o);
            if (t >= o) y += z;
        }
        wtot[t] = y - w;
    }
    __syncthreads();
    int incl = wtot[wid] + x;
    g_blocal[c * B + t] = incl - v;       // exclusive
    if (t == B - 1) g_ctotal[c] = incl;
}

// ---------------- kernel 3: scatter (per-block base scan + smem cursors) --
__global__ void __launch_bounds__(256) k_scatter(const int* __restrict__ l32, int n) {
    __shared__ int cur[C];
    __shared__ int wt4[4];
    int b = blockIdx.x;
    int t = threadIdx.x;
    int st = probe_stride(l32, n, t);

    int v = 0, x = 0;
    if (t < 128) {
        v = (t < C) ? g_ctotal[t] : 0;
        x = v;
        #pragma unroll
        for (int o = 1; o < 32; o <<= 1) {
            int y = __shfl_up_sync(0xffffffffu, x, o);
            if ((t & 31) >= o) x += y;
        }
        if ((t & 31) == 31) wt4[t >> 5] = x;
    }
    __syncthreads();
    if (t < C) {
        int base = 0;
        #pragma unroll
        for (int w = 0; w < 4; w++) base += (w < (t >> 5)) ? wt4[w] : 0;
        int excl = base + x - v;
        cur[t] = excl + g_blocal[t * B + b];
        if (b == 0) { g_offset[t] = excl; g_count[t] = v; }
    }
    __syncthreads();

    int chunk = (n + B - 1) / B;
    int lo = b * chunk, hi = min(n, lo + chunk);
    for (int i = lo + t; i < hi; i += blockDim.x) {
        int c   = l32[(size_t)i * st];
        int pos = atomicAdd(&cur[c], 1);
        g_sorted[pos] = i;
    }
}

// ---------------- kernel 4: per-class sums + fused mean/norm finalize -----
// Ascending class order; at kernel end L2 retains the HIGH classes' rows.
__global__ void __launch_bounds__(128) k_classsum(const float* __restrict__ feat) {
    int c   = blockIdx.x / S1;
    int s   = blockIdx.x % S1;
    int beg = g_offset[c];
    int cnt = g_count[c];
    int per = (cnt + S1 - 1) / S1;
    int lo  = beg + s * per;
    int hi  = min(beg + cnt, lo + per);

    const float4* f4 = (const float4*)feat;
    int col = threadIdx.x;                      // 0..127

    if (lo < hi) {
        float4 acc = make_float4(0.f, 0.f, 0.f, 0.f);
        int j = lo;
        for (; j + 3 < hi; j += 4) {            // MLP = 4 independent rows
            int r0 = g_sorted[j], r1 = g_sorted[j + 1];
            int r2 = g_sorted[j + 2], r3 = g_sorted[j + 3];
            float4 v0 = f4[(size_t)r0 * D4 + col];
            float4 v1 = f4[(size_t)r1 * D4 + col];
            float4 v2 = f4[(size_t)r2 * D4 + col];
            float4 v3 = f4[(size_t)r3 * D4 + col];
            acc.x += v0.x + v1.x + v2.x + v3.x;
            acc.y += v0.y + v1.y + v2.y + v3.y;
            acc.z += v0.z + v1.z + v2.z + v3.z;
            acc.w += v0.w + v1.w + v2.w + v3.w;
        }
        for (; j < hi; j++) {
            float4 v = f4[(size_t)g_sorted[j] * D4 + col];
            acc.x += v.x; acc.y += v.y; acc.z += v.z; acc.w += v.w;
        }
        float* dst = &g_sum[c * D + 4 * col];
        atomicAdd(dst + 0, acc.x);
        atomicAdd(dst + 1, acc.y);
        atomicAdd(dst + 2, acc.z);
        atomicAdd(dst + 3, acc.w);
    }

    // last segment block of this class finalizes mean + inverse norm.
    // Canonical threadFenceReduction: barrier, then fence + ticket.
    __syncthreads();
    __shared__ int s_rank;
    if (threadIdx.x == 0) {
        __threadfence();
        s_rank = atomicAdd(&g_done[c], 1);
    }
    __syncthreads();
    if (s_rank == S1 - 1) {
        int t = threadIdx.x;
        float inv = 1.0f / fmaxf((float)cnt, 1.0f);
        float4 sv = __ldcg((const float4*)&g_sum[c * D] + t);  // L2-coherent
        float4 m  = make_float4(sv.x * inv, sv.y * inv, sv.z * inv, sv.w * inv);
        ((float4*)&g_mean[c * D])[t] = m;
        float loc = m.x * m.x + m.y * m.y + m.z * m.z + m.w * m.w;
        for (int o = 16; o; o >>= 1) loc += __shfl_xor_sync(0xffffffffu, loc, o);
        __shared__ float wsum[4];
        if ((t & 31) == 0) wsum[t >> 5] = loc;
        __syncthreads();
        if (t == 0) {
            float tot = wsum[0] + wsum[1] + wsum[2] + wsum[3];
            g_invn[c] = 1.0f / fmaxf(sqrtf(tot), EPSF);
        }
    }
}

// ---------------- kernel 5: fused dot + feat norm + output ----------------
// Descending class order: first classes read are the ones pass 1 streamed
// last — still resident in the 126 MB L2.
__global__ void __launch_bounds__(256) k_out(const float* __restrict__ feat,
                                             float* __restrict__ out) {
    __shared__ float4 sm[D4];
    int c = (C - 1) - blockIdx.x / S2;     // reversed class order
    int s = blockIdx.x % S2;
    if (threadIdx.x < D4)
        sm[threadIdx.x] = ((const float4*)&g_mean[c * D])[threadIdx.x];
    __syncthreads();

    int beg = g_offset[c];
    int cnt = g_count[c];
    int per = (cnt + S2 - 1) / S2;
    int lo  = beg + s * per;
    int hi  = min(beg + cnt, lo + per);

    int warp = threadIdx.x >> 5;
    int lane = threadIdx.x & 31;
    float invn = g_invn[c];
    const float4* f4 = (const float4*)feat;

    for (int j = lo + warp; j < hi; j += 8) {
        int r = g_sorted[j];
        const float4* fr = f4 + (size_t)r * D4;
        float dot = 0.f, nf = 0.f;
        #pragma unroll
        for (int it = 0; it < 4; it++) {
            int c4 = lane + 32 * it;
            float4 f = fr[c4];
            float4 m = sm[c4];
            dot += f.x * m.x + f.y * m.y + f.z * m.z + f.w * m.w;
            nf  += f.x * f.x + f.y * f.y + f.z * f.z + f.w * f.w;
        }
        #pragma unroll
        for (int o = 16; o; o >>= 1) {
            dot += __shfl_xor_sync(0xffffffffu, dot, o);
            nf  += __shfl_xor_sync(0xffffffffu, nf, o);
        }
        if (lane == 0)
            out[r] = dot * invn / fmaxf(sqrtf(nf), EPSF);
    }
}

// ---------------- launch ---------------------------------------------------
extern "C" void kernel_launch(void* const* d_in, const int* in_sizes, int n_in,
                              void* d_out, int out_size) {
    const float* feat = (const float*)d_in[0];
    const int*   l32  = (const int*)d_in[1];   // int32 or int64; probed on device
    float*       out  = (float*)d_out;
    int n = in_sizes[1];

    k_hist<<<B, 256>>>(l32, n);
    k_scanb<<<C, B>>>();
    k_scatter<<<B, 256>>>(l32, n);
    k_classsum<<<C * S1, 128>>>(feat);
    k_out<<<C * S2, 256>>>(feat, out);
}

// round 11
// speedup vs baseline: 1.1345x; 1.1345x over previous
#include <cuda_runtime.h>
#include <cuda_pipeline_primitives.h>
#include <math.h>

#define NMAX 100000
#define D    512
#define D4   128          // D / 4 (float4 columns)
#define C    100
#define B    512          // sort blocks
#define S1   24           // segments per class, pass 1
#define S2   24           // segments per class, pass 2
#define DEPTH 6           // cp.async row pipeline depth
#define IDXCAP 128        // per-segment index capacity (rows/seg <= ~48)
#define EPSF 1e-8f

// ---------------- device scratch (static; no allocations allowed) ----------
__device__ int   g_bhist[C * B];   // per-(class, sortblock) counts
__device__ int   g_blocal[C * B];  // exclusive scan of g_bhist within each class
__device__ int   g_ctotal[C];      // per-class totals
__device__ int   g_offset[C];      // class base offsets
__device__ int   g_count[C];
__device__ int   g_done[C];        // classsum segment completion counters
__device__ int   g_sorted[NMAX];
__device__ float g_sum[C * D];
__device__ float g_mean[C * D];
__device__ float g_invn[C];        // 1 / max(||mean_c||, eps)

// Label-dtype probe over the FIXED window [0, min(64,n)) — in-bounds and
// identical in every block. int64 labels in [0,100): odd int32 words all 0.
// Returns element stride in int32 units: 1 for int32, 2 for int64.
__device__ __forceinline__ int probe_stride(const int* __restrict__ l32,
                                            int n, int tid) {
    __shared__ int s_st;
    if (tid < 32) {
        int lim = (n < 64) ? n : 64;
        int any = 0;
        for (int i = tid; i < lim; i += 32)
            any |= l32[2 * (size_t)i + 1];
        any = __any_sync(0xffffffffu, any != 0);
        if (tid == 0) s_st = any ? 1 : 2;
    }
    __syncthreads();
    return s_st;
}

// ---------------- kernel 1: zero sums + per-block class histogram ---------
__global__ void __launch_bounds__(256) k_hist(const int* __restrict__ l32, int n) {
    __shared__ int sh[C];
    int b = blockIdx.x;
    {
        float4* z4 = (float4*)&g_sum[b * 100];   // C*D = B * 100 floats
        for (int i = threadIdx.x; i < 25; i += blockDim.x)
            z4[i] = make_float4(0.f, 0.f, 0.f, 0.f);
    }
    for (int i = threadIdx.x; i < C; i += blockDim.x) sh[i] = 0;
    __syncthreads();

    int st = probe_stride(l32, n, threadIdx.x);
    int chunk = (n + B - 1) / B;
    int lo = b * chunk, hi = min(n, lo + chunk);

    for (int i = lo + threadIdx.x; i < hi; i += blockDim.x)
        atomicAdd(&sh[l32[(size_t)i * st]], 1);
    __syncthreads();
    for (int c = threadIdx.x; c < C; c += blockDim.x)
        g_bhist[c * B + b] = sh[c];
}

// ---------------- kernel 2: per-class exclusive scan over the B blocks ----
__global__ void __launch_bounds__(B) k_scanb() {
    int c = blockIdx.x;
    int t = threadIdx.x;                  // 0..511, 16 warps
    if (t == 0) g_done[c] = 0;
    int v = g_bhist[c * B + t];

    int x = v;
    #pragma unroll
    for (int o = 1; o < 32; o <<= 1) {
        int y = __shfl_up_sync(0xffffffffu, x, o);
        if ((t & 31) >= o) x += y;
    }
    __shared__ int wtot[16];
    int wid = t >> 5, lane = t & 31;
    if (lane == 31) wtot[wid] = x;
    __syncthreads();
    if (t < 16) {
        int w = wtot[t];
        int y = w;
        #pragma unroll
        for (int o = 1; o < 16; o <<= 1) {
            int z = __shfl_up_sync(0x0000ffffu, y, o);
            if (t >= o) y += z;
        }
        wtot[t] = y - w;
    }
    __syncthreads();
    int incl = wtot[wid] + x;
    g_blocal[c * B + t] = incl - v;       // exclusive
    if (t == B - 1) g_ctotal[c] = incl;
}

// ---------------- kernel 3: scatter (per-block base scan + smem cursors) --
__global__ void __launch_bounds__(256) k_scatter(const int* __restrict__ l32, int n) {
    __shared__ int cur[C];
    __shared__ int wt4[4];
    int b = blockIdx.x;
    int t = threadIdx.x;
    int st = probe_stride(l32, n, t);

    int v = 0, x = 0;
    if (t < 128) {
        v = (t < C) ? g_ctotal[t] : 0;
        x = v;
        #pragma unroll
        for (int o = 1; o < 32; o <<= 1) {
            int y = __shfl_up_sync(0xffffffffu, x, o);
            if ((t & 31) >= o) x += y;
        }
        if ((t & 31) == 31) wt4[t >> 5] = x;
    }
    __syncthreads();
    if (t < C) {
        int base = 0;
        #pragma unroll
        for (int w = 0; w < 4; w++) base += (w < (t >> 5)) ? wt4[w] : 0;
        int excl = base + x - v;
        cur[t] = excl + g_blocal[t * B + b];
        if (b == 0) { g_offset[t] = excl; g_count[t] = v; }
    }
    __syncthreads();

    int chunk = (n + B - 1) / B;
    int lo = b * chunk, hi = min(n, lo + chunk);
    for (int i = lo + t; i < hi; i += blockDim.x) {
        int c   = l32[(size_t)i * st];
        int pos = atomicAdd(&cur[c], 1);
        g_sorted[pos] = i;
    }
}

// ---------------- kernel 4: per-class sums via cp.async row pipeline ------
// Thread t owns float4 column t and reads ONLY the 16B it itself issued a
// cp.async for — no cross-thread smem visibility needed, so no per-slot
// barrier. Row indices prefetched to smem first (kills the idx->feat
// dependent-load chain).
__global__ void __launch_bounds__(128) k_classsum(const float* __restrict__ feat) {
    __shared__ int    sidx[IDXCAP];
    __shared__ float4 ring[DEPTH][128];

    int c   = blockIdx.x / S1;
    int s   = blockIdx.x % S1;
    int beg = g_offset[c];
    int cnt = g_count[c];
    int per = (cnt + S1 - 1) / S1;
    int lo  = beg + s * per;
    int hi  = min(beg + cnt, lo + per);
    int m   = hi - lo;                          // rows in this segment
    if (m > IDXCAP) m = IDXCAP;                 // safety (never hit: m<=~48)

    int t = threadIdx.x;                        // 0..127
    for (int k = t; k < m; k += 128)
        sidx[k] = g_sorted[lo + k];
    __syncthreads();

    const float4* f4 = (const float4*)feat;
    float4 acc = make_float4(0.f, 0.f, 0.f, 0.f);

    if (m > 0) {
        int pre = (m < DEPTH) ? m : DEPTH;
        int wslot = 0;
        for (int i = 0; i < pre; i++) {
            __pipeline_memcpy_async(&ring[wslot][t],
                                    f4 + (size_t)sidx[i] * D4 + t, 16);
            __pipeline_commit();
            if (++wslot == DEPTH) wslot = 0;
        }
        int issued = pre;
        int j = 0, rslot = 0;
        // steady state: issued == j + DEPTH
        for (; issued < m; j++) {
            __pipeline_wait_prior(DEPTH - 1);   // oldest (row j) complete
            float4 v = ring[rslot][t];
            acc.x += v.x; acc.y += v.y; acc.z += v.z; acc.w += v.w;
            if (++rslot == DEPTH) rslot = 0;
            __pipeline_memcpy_async(&ring[wslot][t],
                                    f4 + (size_t)sidx[issued] * D4 + t, 16);
            __pipeline_commit();
            if (++wslot == DEPTH) wslot = 0;
            issued++;
        }
        __pipeline_wait_prior(0);               // drain: all rows landed
        for (; j < m; j++) {
            float4 v = ring[rslot][t];
            acc.x += v.x; acc.y += v.y; acc.z += v.z; acc.w += v.w;
            if (++rslot == DEPTH) rslot = 0;
        }
        float* dst = &g_sum[c * D + 4 * t];
        atomicAdd(dst + 0, acc.x);
        atomicAdd(dst + 1, acc.y);
        atomicAdd(dst + 2, acc.z);
        atomicAdd(dst + 3, acc.w);
    }

    // last segment block of this class finalizes mean + inverse norm.
    // Canonical threadFenceReduction: barrier, then fence + ticket.
    __syncthreads();
    __shared__ int s_rank;
    if (t == 0) {
        __threadfence();
        s_rank = atomicAdd(&g_done[c], 1);
    }
    __syncthreads();
    if (s_rank == S1 - 1) {
        float inv = 1.0f / fmaxf((float)cnt, 1.0f);
        float4 sv = __ldcg((const float4*)&g_sum[c * D] + t);  // L2-coherent
        float4 mm = make_float4(sv.x * inv, sv.y * inv, sv.z * inv, sv.w * inv);
        ((float4*)&g_mean[c * D])[t] = mm;
        float loc = mm.x * mm.x + mm.y * mm.y + mm.z * mm.z + mm.w * mm.w;
        for (int o = 16; o; o >>= 1) loc += __shfl_xor_sync(0xffffffffu, loc, o);
        __shared__ float wsum[4];
        if ((t & 31) == 0) wsum[t >> 5] = loc;
        __syncthreads();
        if (t == 0) {
            float tot = wsum[0] + wsum[1] + wsum[2] + wsum[3];
            g_invn[c] = 1.0f / fmaxf(sqrtf(tot), EPSF);
        }
    }
}

// ---------------- kernel 5: fused dot + feat norm + output ----------------
// Descending class order: first classes read are the ones pass 1 streamed
// last — still resident in the 126 MB L2.
__global__ void __launch_bounds__(256) k_out(const float* __restrict__ feat,
                                             float* __restrict__ out) {
    __shared__ float4 sm[D4];
    int c = (C - 1) - blockIdx.x / S2;     // reversed class order
    int s = blockIdx.x % S2;
    if (threadIdx.x < D4)
        sm[threadIdx.x] = ((const float4*)&g_mean[c * D])[threadIdx.x];
    __syncthreads();

    int beg = g_offset[c];
    int cnt = g_count[c];
    int per = (cnt + S2 - 1) / S2;
    int lo  = beg + s * per;
    int hi  = min(beg + cnt, lo + per);

    int warp = threadIdx.x >> 5;
    int lane = threadIdx.x & 31;
    float invn = g_invn[c];
    const float4* f4 = (const float4*)feat;

    for (int j = lo + warp; j < hi; j += 8) {
        int r = g_sorted[j];
        const float4* fr = f4 + (size_t)r * D4;
        float dot = 0.f, nf = 0.f;
        #pragma unroll
        for (int it = 0; it < 4; it++) {
            int c4 = lane + 32 * it;
            float4 f = fr[c4];
            float4 m = sm[c4];
            dot += f.x * m.x + f.y * m.y + f.z * m.z + f.w * m.w;
            nf  += f.x * f.x + f.y * f.y + f.z * f.z + f.w * f.w;
        }
        #pragma unroll
        for (int o = 16; o; o >>= 1) {
            dot += __shfl_xor_sync(0xffffffffu, dot, o);
            nf  += __shfl_xor_sync(0xffffffffu, nf, o);
        }
        if (lane == 0)
            out[r] = dot * invn / fmaxf(sqrtf(nf), EPSF);
    }
}

// ---------------- launch ---------------------------------------------------
extern "C" void kernel_launch(void* const* d_in, const int* in_sizes, int n_in,
                              void* d_out, int out_size) {
    const float* feat = (const float*)d_in[0];
    const int*   l32  = (const int*)d_in[1];   // int32 or int64; probed on device
    float*       out  = (float*)d_out;
    int n = in_sizes[1];

    k_hist<<<B, 256>>>(l32, n);
    k_scanb<<<C, B>>>();
    k_scatter<<<B, 256>>>(l32, n);
    k_classsum<<<C * S1, 128>>>(feat);
    k_out<<<C * S2, 256>>>(feat, out);
}